// round 15
// baseline (speedup 1.0000x reference)
#include <cuda_runtime.h>

#define G 128
#define H 64
#define Q 32

// ---------------- constant weights (warp-uniform access only) ---------------
__constant__ float cW2[3*3*3*16*4];     // (3,3,3,16,4) = 1728
__constant__ float cWt1[2*2*2*4*16];    // (2,2,2,4,16)
__constant__ float cWt2[2*2*2*16];      // (2,2,2,16,1)

// ---------------- scratch (device globals; no allocs allowed) ---------------
__device__ float g_hp1[2u*64*64*64*16]; // pooled stage-1 activations, NDHWC
__device__ float g_hp2[2u*32*32*32*4];  // pooled stage-2 activations, NDHWC
__device__ unsigned char g_m1[2u*64*64*64];
__device__ unsigned char g_m2[2u*32*32*32];

__device__ __forceinline__ float frelu(float v) { return v > 0.f ? v : 0.f; }
__device__ __forceinline__ float fsig(float v) { return 1.f / (1.f + __expf(-v)); }

// packed fp32x2 helpers (Blackwell FFMA2 — only reachable via PTX)
__device__ __forceinline__ unsigned long long dup2(float a) {
    unsigned long long r;
    asm("mov.b64 %0, {%1, %1};" : "=l"(r) : "f"(a));
    return r;
}
__device__ __forceinline__ void fma2(unsigned long long& d,
                                     unsigned long long a, unsigned long long b) {
    asm("fma.rn.f32x2 %0, %1, %2, %0;" : "+l"(d) : "l"(a), "l"(b));
}
__device__ __forceinline__ float lo32(unsigned long long v) {
    return __uint_as_float((unsigned)v);
}
__device__ __forceinline__ float hi32(unsigned long long v) {
    return __uint_as_float((unsigned)(v >> 32));
}

// ============================================================================
// K1: xm = x*(occ==0); h1 = relu(conv3(xm,W1))*m0; hp1 = maxpool2(h1)
// Compacted active list; 8 threads/voxel, FFMA2 channel pairs. Halo stored
// PRE-DUPLICATED as float2 so one aligned LDS.64 feeds FFMA2 (no dup movs).
// Work + atomics spread over all 8 warps (32 voxels/pass). Emits m1 bytes.
// ============================================================================
__global__ __launch_bounds__(256) void k1_conv1_pool(const float* __restrict__ x,
                                                     const int* __restrict__ occ,
                                                     const float* __restrict__ W1)
{
    __shared__ float2 xs[1000];             // 10^3 masked-x halo, dup'd (8KB)
    __shared__ unsigned short lst[512];     // compacted active fine voxels
    __shared__ int cnt;
    __shared__ int cellact[64];             // any-active per pooled cell
    __shared__ float pl[1024];              // pooled accum [cell][ch]

    int bi  = blockIdx.x;
    int b   = bi >> 12;
    int tz  = (bi >> 8) & 15, ty = (bi >> 4) & 15, tx = bi & 15;
    int tid = threadIdx.x;
    int p   = tid & 7;      // channel pair (ch = 2p, 2p+1)
    int g   = tid >> 3;     // voxel group 0..31

    // per-thread ch-pair weights: W1 (27,16) -> u64 pairs, contiguous
    unsigned long long w[27];
    const unsigned long long* W1p = (const unsigned long long*)W1;
    #pragma unroll
    for (int t = 0; t < 27; t++) w[t] = W1p[t*8 + p];

    if (tid == 0) cnt = 0;
    if (tid < 64) cellact[tid] = 0;
    #pragma unroll
    for (int it = 0; it < 4; it++) pl[tid + it*256] = 0.f;
    __syncthreads();

    int fz0 = tz*8, fy0 = ty*8, fx0 = tx*8;
    int baseb = b * (G*G*G);

    #pragma unroll
    for (int it = 0; it < 4; it++) {
        int i = tid + it*256;
        if (i < 1000) {
            int z = i/100, y = (i/10)%10, xx = i%10;
            int gz = fz0+z-1, gy = fy0+y-1, gx = fx0+xx-1;
            float v = 0.f;
            int   o = 1;
            bool inb = ((unsigned)gz < G) & ((unsigned)gy < G) & ((unsigned)gx < G);
            if (inb) {
                int idx = baseb + (gz*G + gy)*G + gx;
                o = occ[idx];
                v = x[idx];
            }
            bool act = inb && (o == 0);
            float vv = act ? v : 0.f;
            xs[i] = make_float2(vv, vv);
            if (act && z >= 1 && z <= 8 && y >= 1 && y <= 8 && xx >= 1 && xx <= 8) {
                int lz = z-1, ly = y-1, lx = xx-1;
                int pp = atomicAdd(&cnt, 1);
                lst[pp] = (unsigned short)((lz<<6) | (ly<<3) | lx);
                atomicOr(&cellact[((lz>>1)<<4) | ((ly>>1)<<2) | (lx>>1)], 1);
            }
        }
    }
    __syncthreads();

    int n = cnt;
    for (int base = 0; base < n; base += 32) {
        int vi = base + g;
        if (vi < n) {
            int code = lst[vi];
            int lz = code >> 6, ly = (code >> 3) & 7, lx = code & 7;
            const float2* xp = &xs[lz*100 + ly*10 + lx];
            unsigned long long acc = 0ull;
            #pragma unroll
            for (int dz = 0; dz < 3; dz++)
            #pragma unroll
            for (int dy = 0; dy < 3; dy++)
            #pragma unroll
            for (int dx = 0; dx < 3; dx++)
                fma2(acc,
                     *(const unsigned long long*)&xp[dz*100 + dy*10 + dx],
                     w[(dz*3+dy)*3+dx]);
            float a0 = frelu(lo32(acc));
            float a1 = frelu(hi32(acc));
            int cell = ((lz>>1)<<4) | ((ly>>1)<<2) | (lx>>1);
            atomicMax((int*)&pl[cell*16 + 2*p    ], __float_as_int(a0)); // nonneg
            atomicMax((int*)&pl[cell*16 + 2*p + 1], __float_as_int(a1));
        }
    }
    __syncthreads();

    #pragma unroll
    for (int it = 0; it < 4; it++) {
        int i = tid + it*256;
        int cell = i >> 4, c2 = i & 15;
        int cz = cell >> 4, cy = (cell >> 2) & 3, cx = cell & 3;
        int pz = tz*4 + cz, py = ty*4 + cy, px = tx*4 + cx;
        int pidx = ((b*H + pz)*H + py)*H + px;
        g_hp1[(pidx << 4) + c2] = pl[i];
        if (c2 == 0) g_m1[pidx] = (unsigned char)(cellact[cell] != 0);
    }
}

// ============================================================================
// K2 (R9 proven version): h2 = relu(conv3(hp1,W2))*m1; hp2 = maxpool2(h2).
// 512 threads, 1 voxel/thread, compacted active list. Weights in constant
// memory as co-pair u64 (uniform LDCU); FFMA2 over co-pairs with dup'd input.
// XOR-swizzled ts quads kill LDS bank conflicts. Emits m2.
// ============================================================================
__global__ __launch_bounds__(512) void k2_conv2_pool()
{
    extern __shared__ float ts[];            // 10*10*10*16 floats = 64000 B
    __shared__ float hs[512*4];              // per-voxel relu'd masked outputs
    __shared__ unsigned char sm1[512];       // per-voxel m1
    __shared__ unsigned short lst[512];      // compacted active voxels
    __shared__ int cnt;

    int bi  = blockIdx.x;
    int b   = bi >> 9;
    int t   = bi & 511;
    int tz  = t >> 6, ty = (t >> 3) & 7, tx = t & 7;
    int tid = threadIdx.x;

    if (tid == 0) cnt = 0;
    *(float4*)&hs[tid*4] = make_float4(0.f, 0.f, 0.f, 0.f);

    int fz0 = tz*8, fy0 = ty*8, fx0 = tx*8;

    // halo load with per-voxel XOR slot swizzle: data quad q -> slot q^(i&3)
    for (int i = tid; i < 1000; i += 512) {
        int z = i/100, y = (i/10)%10, xx = i%10;
        int gz = fz0+z-1, gy = fy0+y-1, gx = fx0+xx-1;
        float4* dst = (float4*)&ts[i*16];
        int s = i & 3;
        if ((unsigned)gz < H && (unsigned)gy < H && (unsigned)gx < H) {
            const float4* src = (const float4*)&g_hp1[(((b*H+gz)*H + gy)*H + gx)*16];
            dst[0^s] = src[0]; dst[1^s] = src[1]; dst[2^s] = src[2]; dst[3^s] = src[3];
        } else {
            float4 zz = make_float4(0.f, 0.f, 0.f, 0.f);
            dst[0] = zz; dst[1] = zz; dst[2] = zz; dst[3] = zz;
        }
    }

    // m1 + compaction
    {
        int lz = tid >> 6, ly = (tid >> 3) & 7, lx = tid & 7;
        int uz = fz0 + lz, uy = fy0 + ly, ux = fx0 + lx;
        unsigned char m1 = g_m1[((b*H + uz)*H + uy)*H + ux];
        sm1[tid] = m1;
        if (m1) {
            int p = atomicAdd(&cnt, 1);
            lst[p] = (unsigned short)tid;
        }
    }
    __syncthreads();

    int n = cnt;
    if (tid < n) {
        int code = lst[tid];
        int lz = code >> 6, ly = (code >> 3) & 7, lx = code & 7;

        unsigned long long a0 = 0ull, a1 = 0ull;   // (co0,co1),(co2,co3)

        #pragma unroll 1
        for (int dz = 0; dz < 3; dz++) {
            #pragma unroll 1
            for (int dy = 0; dy < 3; dy++) {
                int rowb = (lz+dz)*100 + (ly+dy)*10 + lx;
                int wb   = (dz*3 + dy)*3;
                #pragma unroll
                for (int dx = 0; dx < 3; dx++) {
                    int row = rowb + dx;
                    const float4* tp = (const float4*)&ts[row*16];
                    int s = row & 3;
                    const unsigned long long* wp =
                        (const unsigned long long*)&cW2[(wb + dx)*64];
                    #pragma unroll
                    for (int cq = 0; cq < 4; cq++) {
                        float v[4];
                        *(float4*)v = tp[cq ^ s];
                        #pragma unroll
                        for (int j = 0; j < 4; j++) {
                            unsigned long long d = dup2(v[j]);
                            fma2(a0, d, wp[(cq*4+j)*2 + 0]);
                            fma2(a1, d, wp[(cq*4+j)*2 + 1]);
                        }
                    }
                }
            }
        }
        float o0 = frelu(lo32(a0));
        float o1 = frelu(hi32(a0));
        float o2 = frelu(lo32(a1));
        float o3 = frelu(hi32(a1));
        *(float4*)&hs[code*4] = make_float4(o0, o1, o2, o3);
    }
    __syncthreads();

    // pool 2x2x2 + m2
    if (tid < 256) {
        int cell = tid >> 2, co = tid & 3;
        int cz = cell >> 4, cy = (cell >> 2) & 3, cx = cell & 3;
        float mv = 0.f;
        int anym = 0;
        #pragma unroll
        for (int k = 0; k < 8; k++) {
            int child = (((cz*2 + ((k>>2)&1)) << 6) |
                         ((cy*2 + ((k>>1)&1)) << 3) |
                          (cx*2 + (k&1)));
            mv = fmaxf(mv, hs[child*4 + co]);
            anym |= sm1[child];
        }
        int pz = tz*4 + cz, py = ty*4 + cy, px = tx*4 + cx;
        int cidx = ((b*Q + pz)*Q + py)*Q + px;
        g_hp2[cidx*4 + co] = mv;
        if (co == 0) g_m2[cidx] = (unsigned char)(anym != 0);
    }
}

// ============================================================================
// K3: fused decoder, thread = (cell, dz, dy) -> 4x parallelism vs R9.
// Warp lanes = consecutive ix -> perfectly coalesced float4 stores.
// m2 is ~99.9% dense: no divergent zero path, just scale by m2.
//   h3(2i+d,co) = relu(sum_ci hp2(i,ci)*Wt1[1-d][ci][co])   (conv_transpose flip)
//   out(2u+e)   = sigmoid(sum_co h3(u,co)*Wt2[1-e][co]) * m2
// ============================================================================
__global__ __launch_bounds__(256) void k3_tconv(float* __restrict__ out)
{
    int bi  = blockIdx.x;                 // B*512 blocks
    int tid = threadIdx.x;
    int ix  = tid & 31;
    int q   = (tid >> 5) & 3;
    int dz  = q >> 1, dy = q & 1;
    int iy  = ((bi & 15) << 1) | (tid >> 7);
    int iz  = (bi >> 4) & 31;
    int b   = bi >> 9;

    int cell  = ((b*Q + iz)*Q + iy)*Q + ix;
    float m2f = (float)g_m2[cell];
    const float4 hin = *(const float4*)&g_hp2[cell*4];

    // h3 for this (dz,dy), dx=0 (a) and dx=1 (b); kernel flipped: 1-d
    float h3a[16], h3b[16];
    {
        const float* wA = &cWt1[(((1-dz)*2 + (1-dy))*2 + 1)*64]; // dx=0
        const float* wB = &cWt1[(((1-dz)*2 + (1-dy))*2 + 0)*64]; // dx=1
        #pragma unroll
        for (int co = 0; co < 16; co++) {
            float va = fmaf(hin.x, wA[co],
                       fmaf(hin.y, wA[16+co],
                       fmaf(hin.z, wA[32+co], hin.w * wA[48+co])));
            float vb = fmaf(hin.x, wB[co],
                       fmaf(hin.y, wB[16+co],
                       fmaf(hin.z, wB[32+co], hin.w * wB[48+co])));
            h3a[co] = frelu(va);
            h3b[co] = frelu(vb);
        }
    }

    int obase = ((b*G + 4*iz + 2*dz)*G + (4*iy + 2*dy))*G + 4*ix;

    #pragma unroll
    for (int ez = 0; ez < 2; ez++)
    #pragma unroll
    for (int ey = 0; ey < 2; ey++) {
        const float* w2e0 = &cWt2[((((1-ez)*2 + (1-ey))*2) + 1)*16]; // ex=0
        const float* w2e1 = &cWt2[((((1-ez)*2 + (1-ey))*2) + 0)*16]; // ex=1
        float sx = 0.f, sy = 0.f, sz = 0.f, sw = 0.f;
        #pragma unroll
        for (int co = 0; co < 16; co++) {
            sx = fmaf(h3a[co], w2e0[co], sx);
            sy = fmaf(h3a[co], w2e1[co], sy);
            sz = fmaf(h3b[co], w2e0[co], sz);
            sw = fmaf(h3b[co], w2e1[co], sw);
        }
        float4 o = make_float4(fsig(sx)*m2f, fsig(sy)*m2f,
                               fsig(sz)*m2f, fsig(sw)*m2f);
        *(float4*)&out[obase + (ez*G + ey)*G] = o;
    }
}

// ============================================================================
extern "C" void kernel_launch(void* const* d_in, const int* in_sizes, int n_in,
                              void* d_out, int out_size)
{
    const float* x   = (const float*)d_in[0];
    const float* W1  = (const float*)d_in[1];
    const float* W2  = (const float*)d_in[2];
    const float* Wt1 = (const float*)d_in[3];
    const float* Wt2 = (const float*)d_in[4];
    const int*   occ = (const int*)  d_in[5];

    int B = in_sizes[0] / (G*G*G);

    cudaMemcpyToSymbolAsync(cW2,  W2,  3*3*3*16*4*sizeof(float), 0, cudaMemcpyDeviceToDevice, 0);
    cudaMemcpyToSymbolAsync(cWt1, Wt1, 2*2*2*4*16*sizeof(float), 0, cudaMemcpyDeviceToDevice, 0);
    cudaMemcpyToSymbolAsync(cWt2, Wt2, 2*2*2*16*sizeof(float),   0, cudaMemcpyDeviceToDevice, 0);

    cudaFuncSetAttribute(k2_conv2_pool, cudaFuncAttributeMaxDynamicSharedMemorySize, 64000);

    k1_conv1_pool<<<B*4096, 256>>>(x, occ, W1);
    k2_conv2_pool<<<B*512, 512, 64000>>>();
    k3_tconv<<<B*512, 256>>>((float*)d_out);
}